// round 1
// baseline (speedup 1.0000x reference)
#include <cuda_runtime.h>
#include <cuda_bf16.h>

// 1024-entry output lookup table: out depends only on q = floor(t*1024).
__device__ float4 g_table[1024];

__global__ void haar_build_table(const float* __restrict__ W1,
                                 const float* __restrict__ b1,
                                 const float* __restrict__ W2,
                                 const float* __restrict__ b2,
                                 const float* __restrict__ W3,
                                 const float* __restrict__ b3) {
    int q = blockIdx.x * blockDim.x + threadIdx.x;
    if (q >= 1024) return;

    float acc[8];
#pragma unroll
    for (int h = 0; h < 8; h++) acc[h] = b1[h];

    // Sparse Haar features: level j contributes sign * W1[row], where
    // row = (2^j - 1) + (q >> (10-j)), sign = +1 if bit (9-j) of q is 0 else -1.
#pragma unroll
    for (int j = 0; j < 10; j++) {
        int k   = q >> (10 - j);
        int row = (1 << j) - 1 + k;
        float s = ((q >> (9 - j)) & 1) ? -1.0f : 1.0f;
        const float4* rp = reinterpret_cast<const float4*>(W1 + row * 8);
        float4 r0 = rp[0];
        float4 r1 = rp[1];
        acc[0] += s * r0.x; acc[1] += s * r0.y;
        acc[2] += s * r0.z; acc[3] += s * r0.w;
        acc[4] += s * r1.x; acc[5] += s * r1.y;
        acc[6] += s * r1.z; acc[7] += s * r1.w;
    }

    float h1[8];
#pragma unroll
    for (int h = 0; h < 8; h++) h1[h] = fmaxf(acc[h], 0.0f);

    float h2[8];
#pragma unroll
    for (int k = 0; k < 8; k++) {
        float v = b2[k];
#pragma unroll
        for (int h = 0; h < 8; h++) v = fmaf(h1[h], W2[h * 8 + k], v);
        h2[k] = fmaxf(v, 0.0f);
    }

    float o[3];
#pragma unroll
    for (int f = 0; f < 3; f++) {
        float v = b3[f];
#pragma unroll
        for (int k = 0; k < 8; k++) v = fmaf(h2[k], W3[k * 3 + f], v);
        o[f] = v;
    }

    g_table[q] = make_float4(o[0], o[1], o[2], 0.0f);
}

__device__ __forceinline__ int q_of(float t) {
    // t*1024 is exact in fp32 (power-of-two scale), so truncation == floor,
    // matching the reference's interval comparisons bit-exactly.
    int q = (int)(t * 1024.0f);
    q = q < 0 ? 0 : (q > 1023 ? 1023 : q);
    return q;
}

__global__ void haar_apply(const float* __restrict__ t,
                           float* __restrict__ out,
                           int n) {
    __shared__ float4 tab[1024];
    for (int i = threadIdx.x; i < 1024; i += blockDim.x)
        tab[i] = g_table[i];
    __syncthreads();

    int n4 = n >> 2;
    const float4* t4 = reinterpret_cast<const float4*>(t);
    float4* o4 = reinterpret_cast<float4*>(out);

    int stride = gridDim.x * blockDim.x;
    for (int i = blockIdx.x * blockDim.x + threadIdx.x; i < n4; i += stride) {
        float4 tv = t4[i];
        float4 r0 = tab[q_of(tv.x)];
        float4 r1 = tab[q_of(tv.y)];
        float4 r2 = tab[q_of(tv.z)];
        float4 r3 = tab[q_of(tv.w)];

        float4 a = make_float4(r0.x, r0.y, r0.z, r1.x);
        float4 b = make_float4(r1.y, r1.z, r2.x, r2.y);
        float4 c = make_float4(r2.z, r3.x, r3.y, r3.z);

        o4[3 * i + 0] = a;
        o4[3 * i + 1] = b;
        o4[3 * i + 2] = c;
    }

    // Scalar tail (n not divisible by 4).
    int tail_start = n4 << 2;
    int gtid = blockIdx.x * blockDim.x + threadIdx.x;
    int tail_n = n - tail_start;
    if (gtid < tail_n) {
        int p = tail_start + gtid;
        float4 r = tab[q_of(t[p])];
        out[3 * p + 0] = r.x;
        out[3 * p + 1] = r.y;
        out[3 * p + 2] = r.z;
    }
}

extern "C" void kernel_launch(void* const* d_in, const int* in_sizes, int n_in,
                              void* d_out, int out_size) {
    const float* t  = (const float*)d_in[0];
    const float* W1 = (const float*)d_in[1];
    const float* b1 = (const float*)d_in[2];
    const float* W2 = (const float*)d_in[3];
    const float* b2 = (const float*)d_in[4];
    const float* W3 = (const float*)d_in[5];
    const float* b3 = (const float*)d_in[6];
    float* out = (float*)d_out;

    int n = in_sizes[0];  // B*T points

    haar_build_table<<<1, 1024>>>(W1, b1, W2, b2, W3, b3);

    int n4 = n >> 2;
    int threads = 256;
    int blocks = (n4 + threads - 1) / threads;
    if (blocks < 1) blocks = 1;
    if (blocks > 1024) blocks = 1024;
    haar_apply<<<blocks, threads>>>(t, out, n);
}

// round 2
// speedup vs baseline: 1.1129x; 1.1129x over previous
#include <cuda_runtime.h>
#include <cuda_bf16.h>

// 1024-entry output lookup table: out depends only on q = floor(t*1024).
__device__ float4 g_table[1024];

__global__ void haar_build_table(const float* __restrict__ W1,
                                 const float* __restrict__ b1,
                                 const float* __restrict__ W2,
                                 const float* __restrict__ b2,
                                 const float* __restrict__ W3,
                                 const float* __restrict__ b3) {
    int q = blockIdx.x * blockDim.x + threadIdx.x;
    if (q >= 1024) return;

    float acc[8];
#pragma unroll
    for (int h = 0; h < 8; h++) acc[h] = b1[h];

    // Sparse Haar features: level j contributes sign * W1[row], where
    // row = (2^j - 1) + (q >> (10-j)), sign = +1 if bit (9-j) of q is 0 else -1.
#pragma unroll
    for (int j = 0; j < 10; j++) {
        int k   = q >> (10 - j);
        int row = (1 << j) - 1 + k;
        float s = ((q >> (9 - j)) & 1) ? -1.0f : 1.0f;
        const float4* rp = reinterpret_cast<const float4*>(W1 + row * 8);
        float4 r0 = __ldg(rp);
        float4 r1 = __ldg(rp + 1);
        acc[0] += s * r0.x; acc[1] += s * r0.y;
        acc[2] += s * r0.z; acc[3] += s * r0.w;
        acc[4] += s * r1.x; acc[5] += s * r1.y;
        acc[6] += s * r1.z; acc[7] += s * r1.w;
    }

    float h1[8];
#pragma unroll
    for (int h = 0; h < 8; h++) h1[h] = fmaxf(acc[h], 0.0f);

    float h2[8];
#pragma unroll
    for (int k = 0; k < 8; k++) {
        float v = b2[k];
#pragma unroll
        for (int h = 0; h < 8; h++) v = fmaf(h1[h], W2[h * 8 + k], v);
        h2[k] = fmaxf(v, 0.0f);
    }

    float o[3];
#pragma unroll
    for (int f = 0; f < 3; f++) {
        float v = b3[f];
#pragma unroll
        for (int k = 0; k < 8; k++) v = fmaf(h2[k], W3[k * 3 + f], v);
        o[f] = v;
    }

    g_table[q] = make_float4(o[0], o[1], o[2], 0.0f);
}

__device__ __forceinline__ int q_of(float t) {
    // t*1024 is exact in fp32 (power-of-two scale), so truncation == floor,
    // matching the reference's interval comparisons bit-exactly.
    int q = (int)(t * 1024.0f);
    q = q < 0 ? 0 : (q > 1023 ? 1023 : q);
    return q;
}

__global__ void __launch_bounds__(256) haar_apply(const float* __restrict__ t,
                                                  float* __restrict__ out,
                                                  int n) {
    int n4 = n >> 2;
    const float4* t4 = reinterpret_cast<const float4*>(t);
    float4* o4 = reinterpret_cast<float4*>(out);
    const float4* tab = g_table;

    int i = blockIdx.x * blockDim.x + threadIdx.x;
    if (i < n4) {
        float4 tv = t4[i];
        float4 r0 = __ldg(tab + q_of(tv.x));
        float4 r1 = __ldg(tab + q_of(tv.y));
        float4 r2 = __ldg(tab + q_of(tv.z));
        float4 r3 = __ldg(tab + q_of(tv.w));

        o4[3 * i + 0] = make_float4(r0.x, r0.y, r0.z, r1.x);
        o4[3 * i + 1] = make_float4(r1.y, r1.z, r2.x, r2.y);
        o4[3 * i + 2] = make_float4(r2.z, r3.x, r3.y, r3.z);
    }

    // Scalar tail (n not divisible by 4) — dead for n = 131072 but kept correct.
    int tail_start = n4 << 2;
    int tail_n = n - tail_start;
    if (i < tail_n) {
        int p = tail_start + i;
        float4 r = __ldg(tab + q_of(t[p]));
        out[3 * p + 0] = r.x;
        out[3 * p + 1] = r.y;
        out[3 * p + 2] = r.z;
    }
}

extern "C" void kernel_launch(void* const* d_in, const int* in_sizes, int n_in,
                              void* d_out, int out_size) {
    const float* t  = (const float*)d_in[0];
    const float* W1 = (const float*)d_in[1];
    const float* b1 = (const float*)d_in[2];
    const float* W2 = (const float*)d_in[3];
    const float* b2 = (const float*)d_in[4];
    const float* W3 = (const float*)d_in[5];
    const float* b3 = (const float*)d_in[6];
    float* out = (float*)d_out;

    int n = in_sizes[0];  // B*T points

    // Spread the latency-bound table build across 8 SMs.
    haar_build_table<<<8, 128>>>(W1, b1, W2, b2, W3, b3);

    int n4 = n >> 2;
    int threads = 256;
    int blocks = (n4 + threads - 1) / threads;
    if (blocks < 1) blocks = 1;
    haar_apply<<<blocks, threads>>>(t, out, n);
}

// round 3
// speedup vs baseline: 1.3424x; 1.2062x over previous
#include <cuda_runtime.h>
#include <cuda_bf16.h>

__device__ __forceinline__ int q_of(float t) {
    // t*1024 is exact in fp32 (power-of-two scale), so truncation == floor,
    // matching the reference's interval comparisons bit-exactly.
    int q = (int)(t * 1024.0f);
    q = q < 0 ? 0 : (q > 1023 ? 1023 : q);
    return q;
}

// Fused: each block builds the full 1024-entry LUT in shared memory
// (redundantly per block — cheaper than a second launch), then applies it.
__global__ void __launch_bounds__(256) haar_fused(const float* __restrict__ t,
                                                  const float* __restrict__ W1,
                                                  const float* __restrict__ b1,
                                                  const float* __restrict__ W2,
                                                  const float* __restrict__ b2,
                                                  const float* __restrict__ W3,
                                                  const float* __restrict__ b3,
                                                  float* __restrict__ out,
                                                  int n) {
    __shared__ float4 tab[1024];

    // ---------- Build phase: 4 entries per thread (2 sibling pairs) ----------
    // Entries q=2m and q=2m+1 share levels 0..8: acc(2m+c) = base ± W1row(level 9).
    float b1r[8];
#pragma unroll
    for (int h = 0; h < 8; h++) b1r[h] = b1[h];

    // Preload W2, W3, biases into registers (tiny, L1/const-cached).
    float w2r[64];
#pragma unroll
    for (int i = 0; i < 64; i++) w2r[i] = W2[i];
    float w3r[24];
#pragma unroll
    for (int i = 0; i < 24; i++) w3r[i] = W3[i];
    float b2r[8];
#pragma unroll
    for (int k = 0; k < 8; k++) b2r[k] = b2[k];
    float b3r[3];
#pragma unroll
    for (int f = 0; f < 3; f++) b3r[f] = b3[f];

#pragma unroll
    for (int p = 0; p < 2; p++) {
        int m = 2 * (int)threadIdx.x + p;   // 0..511

        float base[8];
#pragma unroll
        for (int h = 0; h < 8; h++) base[h] = b1r[h];

        // Levels 0..8 shared by the sibling pair.
#pragma unroll
        for (int j = 0; j < 9; j++) {
            int k   = m >> (9 - j);
            int row = (1 << j) - 1 + k;
            float s = ((m >> (8 - j)) & 1) ? -1.0f : 1.0f;
            const float4* rp = reinterpret_cast<const float4*>(W1 + row * 8);
            float4 r0 = __ldg(rp);
            float4 r1 = __ldg(rp + 1);
            base[0] += s * r0.x; base[1] += s * r0.y;
            base[2] += s * r0.z; base[3] += s * r0.w;
            base[4] += s * r1.x; base[5] += s * r1.y;
            base[6] += s * r1.z; base[7] += s * r1.w;
        }

        // Level 9 row for this pair.
        const float4* rp9 = reinterpret_cast<const float4*>(W1 + (511 + m) * 8);
        float4 f0 = __ldg(rp9);
        float4 f1 = __ldg(rp9 + 1);
        float fine[8] = {f0.x, f0.y, f0.z, f0.w, f1.x, f1.y, f1.z, f1.w};

#pragma unroll
        for (int c = 0; c < 2; c++) {
            float sgn = c ? -1.0f : 1.0f;
            float h1[8];
#pragma unroll
            for (int h = 0; h < 8; h++)
                h1[h] = fmaxf(base[h] + sgn * fine[h], 0.0f);

            float h2[8];
#pragma unroll
            for (int k = 0; k < 8; k++) {
                float v = b2r[k];
#pragma unroll
                for (int h = 0; h < 8; h++) v = fmaf(h1[h], w2r[h * 8 + k], v);
                h2[k] = fmaxf(v, 0.0f);
            }

            float o[3];
#pragma unroll
            for (int f = 0; f < 3; f++) {
                float v = b3r[f];
#pragma unroll
                for (int k = 0; k < 8; k++) v = fmaf(h2[k], w3r[k * 3 + f], v);
                o[f] = v;
            }

            tab[2 * m + c] = make_float4(o[0], o[1], o[2], 0.0f);
        }
    }

    __syncthreads();

    // ---------- Apply phase: 4 points (one float4) per thread ----------
    int n4 = n >> 2;
    const float4* t4 = reinterpret_cast<const float4*>(t);
    float4* o4 = reinterpret_cast<float4*>(out);

    int i = blockIdx.x * blockDim.x + threadIdx.x;
    if (i < n4) {
        float4 tv = t4[i];
        float4 r0 = tab[q_of(tv.x)];
        float4 r1 = tab[q_of(tv.y)];
        float4 r2 = tab[q_of(tv.z)];
        float4 r3 = tab[q_of(tv.w)];

        o4[3 * i + 0] = make_float4(r0.x, r0.y, r0.z, r1.x);
        o4[3 * i + 1] = make_float4(r1.y, r1.z, r2.x, r2.y);
        o4[3 * i + 2] = make_float4(r2.z, r3.x, r3.y, r3.z);
    }

    // Scalar tail (n not divisible by 4) — dead for n = 131072 but kept correct.
    int tail_start = n4 << 2;
    int tail_n = n - tail_start;
    if (i < tail_n) {
        int p = tail_start + i;
        float4 r = tab[q_of(t[p])];
        out[3 * p + 0] = r.x;
        out[3 * p + 1] = r.y;
        out[3 * p + 2] = r.z;
    }
}

extern "C" void kernel_launch(void* const* d_in, const int* in_sizes, int n_in,
                              void* d_out, int out_size) {
    const float* t  = (const float*)d_in[0];
    const float* W1 = (const float*)d_in[1];
    const float* b1 = (const float*)d_in[2];
    const float* W2 = (const float*)d_in[3];
    const float* b2 = (const float*)d_in[4];
    const float* W3 = (const float*)d_in[5];
    const float* b3 = (const float*)d_in[6];
    float* out = (float*)d_out;

    int n = in_sizes[0];  // B*T points

    int n4 = n >> 2;
    int threads = 256;
    int blocks = (n4 + threads - 1) / threads;
    if (blocks < 1) blocks = 1;
    haar_fused<<<blocks, threads>>>(t, W1, b1, W2, b2, W3, b3, out, n);
}

// round 5
// speedup vs baseline: 1.4935x; 1.1126x over previous
#include <cuda_runtime.h>
#include <cuda_bf16.h>

typedef unsigned long long u64;

__device__ __forceinline__ u64 pk2(float lo, float hi) {
    u64 d; asm("mov.b64 %0, {%1, %2};" : "=l"(d) : "f"(lo), "f"(hi)); return d;
}
__device__ __forceinline__ void upk2(u64 v, float& lo, float& hi) {
    asm("mov.b64 {%0, %1}, %2;" : "=f"(lo), "=f"(hi) : "l"(v));
}
__device__ __forceinline__ u64 fma2(u64 a, u64 b, u64 c) {
    u64 d; asm("fma.rn.f32x2 %0, %1, %2, %3;" : "=l"(d) : "l"(a), "l"(b), "l"(c)); return d;
}

__device__ __forceinline__ int q_of(float t) {
    // t*1024 is exact in fp32 (power-of-two scale), so truncation == floor,
    // matching the reference's interval comparisons bit-exactly.
    int q = (int)(t * 1024.0f);
    q = q < 0 ? 0 : (q > 1023 ? 1023 : q);
    return q;
}

// Fused: each block builds the 1024-entry LUT in shared memory using packed
// f32x2 FMAs (half the FMA-pipe work), then applies it to its points.
__global__ void __launch_bounds__(256) haar_fused(const float* __restrict__ t,
                                                  const float* __restrict__ W1,
                                                  const float* __restrict__ b1,
                                                  const float* __restrict__ W2,
                                                  const float* __restrict__ b2,
                                                  const float* __restrict__ W3,
                                                  const float* __restrict__ b3,
                                                  float* __restrict__ out,
                                                  int n) {
    __shared__ float4 tab[1024];
    __shared__ u64 w3s[12];   // w3s[f*4+kk] = (W3[2kk][f], W3[2kk+1][f])

    int tid = threadIdx.x;
    int i = blockIdx.x * blockDim.x + tid;
    int n4 = n >> 2;

    // ---- Prefetch this thread's input points (latency hides behind build) ----
    const float4* t4 = reinterpret_cast<const float4*>(t);
    float4 tv = make_float4(0.f, 0.f, 0.f, 0.f);
    if (i < n4) tv = t4[i];
    int tail_start = n4 << 2;
    int tail_n = n - tail_start;
    float t_tail = 0.f;
    if (i < tail_n) t_tail = t[tail_start + i];

    // ---- Stage packed W3 pairs into smem ----
    if (tid < 12) {
        int f = tid % 3, kk = tid / 3;
        w3s[f * 4 + kk] = pk2(W3[(2 * kk) * 3 + f], W3[(2 * kk + 1) * 3 + f]);
    }

    // ---- Per-thread register preloads (warp-uniform, L1/L2 hits) ----
    const ulonglong2* w2v = reinterpret_cast<const ulonglong2*>(W2);
    u64 w2p[32];
#pragma unroll
    for (int r = 0; r < 16; r++) { ulonglong2 v = w2v[r]; w2p[2*r] = v.x; w2p[2*r+1] = v.y; }

    const ulonglong2* b1v = reinterpret_cast<const ulonglong2*>(b1);
    u64 b1p[4];
    { ulonglong2 v0 = b1v[0], v1 = b1v[1]; b1p[0]=v0.x; b1p[1]=v0.y; b1p[2]=v1.x; b1p[3]=v1.y; }

    const ulonglong2* b2v = reinterpret_cast<const ulonglong2*>(b2);
    u64 b2p[4];
    { ulonglong2 v0 = b2v[0], v1 = b2v[1]; b2p[0]=v0.x; b2p[1]=v0.y; b2p[2]=v1.x; b2p[3]=v1.y; }

    float b3r[3];
#pragma unroll
    for (int f = 0; f < 3; f++) b3r[f] = b3[f];

    __syncthreads();   // w3s visible

    const ulonglong2* w1v = reinterpret_cast<const ulonglong2*>(W1);

    // ---- Build: 4 entries per thread as 2 sibling pairs ----
#pragma unroll
    for (int p = 0; p < 2; p++) {
        int m = 2 * tid + p;   // 0..511

        u64 base2[4];
#pragma unroll
        for (int h = 0; h < 4; h++) base2[h] = b1p[h];

        // Levels 0..8 shared by the sibling pair (entries 2m, 2m+1).
#pragma unroll
        for (int j = 0; j < 9; j++) {
            int k   = m >> (9 - j);
            int row = (1 << j) - 1 + k;
            float s = ((m >> (8 - j)) & 1) ? -1.0f : 1.0f;
            u64 s2 = pk2(s, s);
            ulonglong2 r0 = w1v[row * 2];
            ulonglong2 r1 = w1v[row * 2 + 1];
            base2[0] = fma2(s2, r0.x, base2[0]);
            base2[1] = fma2(s2, r0.y, base2[1]);
            base2[2] = fma2(s2, r1.x, base2[2]);
            base2[3] = fma2(s2, r1.y, base2[3]);
        }

        // Level-9 row for this pair.
        ulonglong2 f0 = w1v[(511 + m) * 2];
        ulonglong2 f1 = w1v[(511 + m) * 2 + 1];
        u64 fine2[4] = { f0.x, f0.y, f1.x, f1.y };

#pragma unroll
        for (int c = 0; c < 2; c++) {
            float sgn = c ? -1.0f : 1.0f;
            u64 sg2 = pk2(sgn, sgn);

            // acc = base + sgn*fine, then ReLU -> broadcast pairs for layer 2.
            u64 bc[8];
#pragma unroll
            for (int h = 0; h < 4; h++) {
                u64 a2 = fma2(sg2, fine2[h], base2[h]);
                float lo, hi; upk2(a2, lo, hi);
                lo = fmaxf(lo, 0.0f); hi = fmaxf(hi, 0.0f);
                bc[2*h]   = pk2(lo, lo);
                bc[2*h+1] = pk2(hi, hi);
            }

            // Layer 2: h2 pairs (k, k+1), k-major packed W2 rows.
            u64 h2p[4];
#pragma unroll
            for (int kk = 0; kk < 4; kk++) h2p[kk] = b2p[kk];
#pragma unroll
            for (int h = 0; h < 8; h++) {
#pragma unroll
                for (int kk = 0; kk < 4; kk++)
                    h2p[kk] = fma2(bc[h], w2p[h * 4 + kk], h2p[kk]);
            }
            // ReLU packed pairs.
#pragma unroll
            for (int kk = 0; kk < 4; kk++) {
                float lo, hi; upk2(h2p[kk], lo, hi);
                h2p[kk] = pk2(fmaxf(lo, 0.0f), fmaxf(hi, 0.0f));
            }

            // Layer 3: per output f, packed dot over k-pairs + horizontal add.
            float o[3];
#pragma unroll
            for (int f = 0; f < 3; f++) {
                u64 acc = pk2(b3r[f], 0.0f);
#pragma unroll
                for (int kk = 0; kk < 4; kk++)
                    acc = fma2(h2p[kk], w3s[f * 4 + kk], acc);
                float lo, hi; upk2(acc, lo, hi);
                o[f] = lo + hi;
            }

            tab[2 * m + c] = make_float4(o[0], o[1], o[2], 0.0f);
        }
    }

    __syncthreads();

    // ---- Apply: 4 points (one float4) per thread ----
    float4* o4 = reinterpret_cast<float4*>(out);
    if (i < n4) {
        float4 r0 = tab[q_of(tv.x)];
        float4 r1 = tab[q_of(tv.y)];
        float4 r2 = tab[q_of(tv.z)];
        float4 r3 = tab[q_of(tv.w)];

        o4[3 * i + 0] = make_float4(r0.x, r0.y, r0.z, r1.x);
        o4[3 * i + 1] = make_float4(r1.y, r1.z, r2.x, r2.y);
        o4[3 * i + 2] = make_float4(r2.z, r3.x, r3.y, r3.z);
    }

    // Scalar tail (n not divisible by 4) — dead for n = 131072 but kept correct.
    if (i < tail_n) {
        int pidx = tail_start + i;
        float4 r = tab[q_of(t_tail)];
        out[3 * pidx + 0] = r.x;
        out[3 * pidx + 1] = r.y;
        out[3 * pidx + 2] = r.z;
    }
}

extern "C" void kernel_launch(void* const* d_in, const int* in_sizes, int n_in,
                              void* d_out, int out_size) {
    const float* t  = (const float*)d_in[0];
    const float* W1 = (const float*)d_in[1];
    const float* b1 = (const float*)d_in[2];
    const float* W2 = (const float*)d_in[3];
    const float* b2 = (const float*)d_in[4];
    const float* W3 = (const float*)d_in[5];
    const float* b3 = (const float*)d_in[6];
    float* out = (float*)d_out;

    int n = in_sizes[0];  // B*T points

    int n4 = n >> 2;
    int threads = 256;
    int blocks = (n4 + threads - 1) / threads;
    if (blocks < 1) blocks = 1;
    haar_fused<<<blocks, threads>>>(t, W1, b1, W2, b2, W3, b3, out, n);
}